// round 17
// baseline (speedup 1.0000x reference)
#include <cuda_runtime.h>
#include <cstdint>

// RandomShiftsAug == integer pixel shift with edge clamp (reference's bilinear
// weights are exactly zero given its linspace/scale arithmetic):
//   out[n,c,j,i] = x[n,c, clamp(j+sy-PAD,0,H-1), clamp(i+sx-PAD,0,W-1)]
//
// R17 = R16 (7-deep MLP direct swizzle) with a 252-thread remap exploiting
// 252 = 12*21: quad index m = tid + 252*i keeps m%21 == tid%21, so the
// column (w4), load column (q), and edge predicates are PER-THREAD CONSTANTS
// and the row is j = tid/21 + 12*i (one add per iteration). Deletes the
// per-iteration div/mod chain, the ww[] array and all tail guards
// (7*252 = 1764 exactly). Same compulsory traffic; pure overhead shave.

#define C_   4
#define W_   84
#define H_   84
#define PAD_ 4
#define W4_  21
#define NBLK (H_ * W4_)   // 1764 quads per plane
#define TPB_ 252          // 12 * 21

__device__ __forceinline__ float sel4(const float4& A, int i) {
    return (i <= 0) ? A.x : (i == 1) ? A.y : (i == 2) ? A.z : A.w;
}

__global__ void __launch_bounds__(TPB_) shift_ilp_kernel(
    const float4* __restrict__ x4,
    const int*    __restrict__ shift,
    float4*       __restrict__ out4)
{
    const int nc  = blockIdx.x;        // n*C + c
    const int n   = nc >> 2;
    const int tid = threadIdx.x;

    int2 sh = __ldg(reinterpret_cast<const int2*>(shift) + n);
    const int sx = sh.x - PAD_;        // [-4, 4], uniform per image
    const int sy = sh.y - PAD_;
    const int r  = sx & 3;             // warp-uniform
    const int d  = (sx - r) >> 2;      // floor(sx/4) in {-1,0,1}

    // per-thread constants (m % 21 == tid % 21 for all iterations)
    const int w4 = tid % W4_;
    const int j0 = tid / W4_;          // 0..11; rows j0 + 12*i
    const int q  = min(max(w4 + d, 0), W4_ - 1);
    const int q1 = min(q + 1, W4_ - 1);
    const bool isL = (sx < 0) & (w4 == 0);
    const bool isR = (sx > 0) & (w4 == W4_ - 1);

    const float4* plane  = x4  + nc * NBLK;
    float4*       oplane = out4 + nc * NBLK;

    float4 A[7], B[7];

    // ---- issue ALL loads back-to-back (MLP 7 or 14) ----
    #pragma unroll
    for (int i = 0; i < 7; ++i) {
        int ys = min(max(j0 + 12 * i + sy, 0), H_ - 1);
        const float4* row = plane + ys * W4_;
        A[i] = __ldg(row + q);
        if (r) B[i] = __ldg(row + q1);
    }

    // ---- compose + store (contiguous, no guards) ----
    #pragma unroll
    for (int i = 0; i < 7; ++i) {
        float4 v;
        if (r == 0)      v = A[i];
        else if (r == 1) v = make_float4(A[i].y, A[i].z, A[i].w, B[i].x);
        else if (r == 2) v = make_float4(A[i].z, A[i].w, B[i].x, B[i].y);
        else             v = make_float4(A[i].w, B[i].x, B[i].y, B[i].z);

        if (isL) {
            // out[k] = in[max(k+sx,0)] = A[max(k+sx,0)]
            v.x = A[i].x;
            v.y = sel4(A[i], 1 + sx);
            v.z = sel4(A[i], 2 + sx);
            v.w = sel4(A[i], 3 + sx);
        } else if (isR) {
            // out[k] = in[80 + min(k+sx,3)] = A[min(k+sx,3)]
            v.x = sel4(A[i], min(0 + sx, 3));
            v.y = sel4(A[i], min(1 + sx, 3));
            v.z = sel4(A[i], min(2 + sx, 3));
            v.w = A[i].w;
        }
        oplane[tid + i * TPB_] = v;
    }
}

extern "C" void kernel_launch(void* const* d_in, const int* in_sizes, int n_in,
                              void* d_out, int out_size)
{
    const float4* x4    = (const float4*)d_in[0];
    const int*    shift = (const int*)d_in[1];
    float4*       out4  = (float4*)d_out;

    int n = in_sizes[0] / (C_ * H_ * W_);
    shift_ilp_kernel<<<n * C_, TPB_>>>(x4, shift, out4);
}